// round 8
// baseline (speedup 1.0000x reference)
#include <cuda_runtime.h>
#include <math.h>

#define BATCH 16
#define NA 3
#define NC 80
#define NCH 85
#define NT 512
#define THRESH 0.6f
#define EPSF 1e-7f

#define N0 307200
#define N1 76800
#define N2 19200

#define NBLK 1184
#define NTHR 256

// float2 items per (b,a) plane and cumulative boundaries
#define PL0 3200
#define PL1 800
#define PL2 200
#define T0v 153600           // p0 float2 items
#define TE1 192000           // +38400 (p1)
#define TE2 201600           // +9600  (p2)

#define NLCLS 122880         // 3*512*80

#define W0 (1.0f / (float)N0)
#define W1 (1.0f / (float)N1)
#define W2 (1.0f / (float)N2)

__device__ float g_obj;
__device__ float g_lcls[3];
__device__ float g_lbox[3];
__device__ float g_nb[3];
__device__ unsigned g_done = 0;

__device__ __forceinline__ float softplus_fast(float x) {
    return fmaxf(x, 0.0f) + __logf(1.0f + __expf(-fabsf(x)));
}

__device__ __forceinline__ float sp2(float2 v) {
    return softplus_fast(v.x) + softplus_fast(v.y);
}

__device__ __forceinline__ float warp_red_f(float v) {
#pragma unroll
    for (int o = 16; o > 0; o >>= 1)
        v += __shfl_down_sync(0xffffffffu, v, o);
    return v;
}

__device__ __forceinline__ bool target_meta(
    const float* __restrict__ targets, const float* __restrict__ anchors,
    float im0, float im1, int s, int t, int H,
    unsigned& off, int& cell, int& a_out,
    float& gx, float& gy, float& gw, float& gh)
{
    const float* tg = targets + t * 6;
    float inv0 = (float)H / im0;
    float inv1 = (float)H / im1;

    gw = tg[4] * inv1;
    gh = tg[5] * inv0;

    float bi = -1.0f, bu = 1.0f;
    int arg = 0;
#pragma unroll
    for (int a = 0; a < 3; a++) {
        float aw = anchors[(s * 3 + a) * 2 + 0] * inv1;
        float ah = anchors[(s * 3 + a) * 2 + 1] * inv0;
        float inter = fminf(aw, gw) * fminf(ah, gh);
        float uni   = aw * ah + gw * gh - inter;
        if (inter * bu > bi * uni) { bi = inter; bu = uni; arg = a; }
    }
    if (!(bi > THRESH * bu)) return false;

    gx = tg[2] * inv1;
    gy = tg[3] * inv0;
    int b  = (int)tg[0];
    int gi = (int)gx;
    int gj = (int)gy;
    if (b  < 0) b  = 0; if (b  > BATCH - 1) b  = BATCH - 1;
    if (gi < 0) gi = 0; if (gi > H - 1)     gi = H - 1;
    if (gj < 0) gj = 0; if (gj > H - 1)     gj = H - 1;
    cell  = ((b * NA + arg) * H + gj) * H + gi;
    off   = (unsigned)((b * NA + arg) * NCH) * (unsigned)(H * H)
          + (unsigned)(gj * H + gi);
    a_out = arg;
    return true;
}

__global__ void __launch_bounds__(NTHR, 8)
yolo_fused(const float* __restrict__ p0,
           const float* __restrict__ p1,
           const float* __restrict__ p2,
           const float* __restrict__ targets,
           const float* __restrict__ anchors,
           const float* __restrict__ image_size,
           float* __restrict__ out)
{
    __shared__ float s_red[8][6];
    __shared__ int   table[1024];

    int tid  = threadIdx.x;
    int blk  = blockIdx.x;
    int lane = tid & 31;
    int wid  = tid >> 5;
    int gt   = blk * NTHR + tid;

    float im0 = image_size[0];
    float im1 = image_size[1];

    // ---------------- objectness: <=1 float2 per thread ----------------
    const float2* p0v = reinterpret_cast<const float2*>(p0);
    const float2* p1v = reinterpret_cast<const float2*>(p1);
    const float2* p2v = reinterpret_cast<const float2*>(p2);

    float obj = 0.0f;
    if (gt < T0v) {
        int ba = gt / PL0;
        int r  = gt - ba * PL0;
        obj = W0 * sp2(p0v[(size_t)(ba * NCH + 4) * PL0 + r]);
    } else if (gt < TE1) {
        int i  = gt - T0v;
        int ba = i / PL1;
        int r  = i - ba * PL1;
        obj = W1 * sp2(p1v[(size_t)(ba * NCH + 4) * PL1 + r]);
    } else if (gt < TE2) {
        int i  = gt - TE1;
        int ba = i / PL2;
        int r  = i - ba * PL2;
        obj = W2 * sp2(p2v[(size_t)(ba * NCH + 4) * PL2 + r]);
    }

    // ---------------- lcls: one item per thread, inline metadata ----------------
    float lc = 0.0f;
    int sA = 2;
    if (gt < NLCLS) {
        int p = gt / NC;
        int j = gt - p * NC;
        sA = p >> 9;            // warp uniform (boundaries at 40960, 81920)
        int t = p & 511;
        int H = (sA == 0) ? 80 : ((sA == 1) ? 40 : 20);

        unsigned off; int cell, a_s; float gx, gy, gw, gh;
        if (target_meta(targets, anchors, im0, im1, sA, t, H,
                        off, cell, a_s, gx, gy, gw, gh)) {
            int HW = H * H;
            const float* pis = (sA == 0) ? p0 : ((sA == 1) ? p1 : p2);
            float x = pis[off + (unsigned)(5 + j) * (unsigned)HW];
            int cls = (int)targets[t * 6 + 1] - 1;
            lc = softplus_fast(x) - ((j == cls) ? x : 0.0f);
        }
    }

    // ---------------- pair work: blocks 0-2 only, 2 targets per thread ----------------
    float lbox = 0.0f, nb = 0.0f;
    bool isTgt = (blk < 3);
    if (isTgt) {
#pragma unroll
        for (int q = 0; q < 4; q++) table[tid + q * 256] = -1;
        __syncthreads();

        int s = blk;
        int H = (s == 0) ? 80 : ((s == 1) ? 40 : 20);
        int HW = H * H;
        const float* pis = (s == 0) ? p0 : ((s == 1) ? p1 : p2);
        float inv0 = (float)H / im0;
        float inv1 = (float)H / im1;
        float ws   = (s == 0) ? W0 : ((s == 1) ? W1 : W2);

#pragma unroll
        for (int q = 0; q < 2; q++) {
            int t = tid + q * NTHR;
            unsigned off; int cell, a_s; float gx, gy, gw, gh;
            if (target_meta(targets, anchors, im0, im1, s, t, H,
                            off, cell, a_s, gx, gy, gw, gh)) {
                nb += 1.0f;

                float aw = anchors[(s * 3 + a_s) * 2 + 0] * inv1;
                float ah = anchors[(s * 3 + a_s) * 2 + 1] * inv0;

                float ps0 = pis[off];
                float ps1 = pis[off + HW];
                float ps2 = pis[off + 2 * HW];
                float ps3 = pis[off + 3 * HW];
                float lg  = pis[off + 4 * HW];

                float pcx = 1.0f / (1.0f + __expf(-ps0));
                float pcy = 1.0f / (1.0f + __expf(-ps1));
                float pw  = fminf(__expf(ps2), 1000.0f) * aw;
                float ph  = fminf(__expf(ps3), 1000.0f) * ah;

                float tcx = gx - floorf(gx);
                float tcy = gy - floorf(gy);

                float px1 = pcx - pw * 0.5f, py1 = pcy - ph * 0.5f;
                float px2 = pcx + pw * 0.5f, py2 = pcy + ph * 0.5f;
                float tx1 = tcx - gw * 0.5f, ty1 = tcy - gh * 0.5f;
                float tx2 = tcx + gw * 0.5f, ty2 = tcy + gh * 0.5f;

                float iw = fmaxf(fminf(px2, tx2) - fmaxf(px1, tx1), 0.0f);
                float ih = fmaxf(fminf(py2, ty2) - fmaxf(py1, ty1), 0.0f);
                float inter = iw * ih;
                float uni   = pw * ph + gw * gh - inter + EPSF;
                float iou   = inter / uni;
                float cw = fmaxf(px2, tx2) - fminf(px1, tx1);
                float ch = fmaxf(py2, ty2) - fminf(py1, ty1);
                float c_area = cw * ch + EPSF;
                float giou = iou - (c_area - uni) / c_area;

                lbox += 1.0f - giou;

                unsigned hsh = ((unsigned)cell * 2654435761u) & 1023u;
                bool owner = false;
                while (true) {
                    int prev = atomicCAS(&table[hsh], -1, cell);
                    if (prev == -1)   { owner = true; break; }
                    if (prev == cell) { break; }
                    hsh = (hsh + 1) & 1023u;
                }
                if (owner) obj += -lg * ws;   // folded tobj correction
            }
        }
    }

    // ---------------- reductions (float, pairwise) ----------------
    obj = warp_red_f(obj);
    lc  = warp_red_f(lc);
    if (isTgt) { lbox = warp_red_f(lbox); nb = warp_red_f(nb); }

    if (lane == 0) {
        s_red[wid][0] = obj;
        s_red[wid][1] = (sA == 0) ? lc : 0.f;
        s_red[wid][2] = (sA == 1) ? lc : 0.f;
        s_red[wid][3] = (sA == 2) ? lc : 0.f;
        s_red[wid][4] = isTgt ? lbox : 0.f;
        s_red[wid][5] = isTgt ? nb   : 0.f;
    }
    __syncthreads();

    if (wid < 6) {
        float v = (lane < 8) ? s_red[lane][wid] : 0.0f;
#pragma unroll
        for (int o = 4; o > 0; o >>= 1)
            v += __shfl_down_sync(0xffffffffu, v, o);
        if (lane == 0) {
            if      (wid == 0) { if (v != 0.0f) atomicAdd(&g_obj, v); }
            else if (wid <  4) { if (v != 0.0f) atomicAdd(&g_lcls[wid - 1], v); }
            else if (isTgt) {
                if (wid == 4) g_lbox[blk] = v;   // single writer per scale
                else          g_nb[blk]   = v;
            }
        }
    }

    // ---------------- finisher ----------------
    __syncthreads();
    if (tid == 0) {
        __threadfence();
        unsigned old = atomicAdd(&g_done, 1u);
        if (old == NBLK - 1) {
            __threadfence();
            float lboxT = 0.f, lclsT = 0.f;
#pragma unroll
            for (int i = 0; i < 3; i++) {
                float nbv = fmaxf(g_nb[i], 1.0f);
                lboxT += g_lbox[i] / nbv;
                lclsT += g_lcls[i] / (nbv * (float)NC);
            }
            float lobjT = g_obj * 64.3f;
            lboxT *= 3.54f;
            lclsT *= 37.4f;
            out[0] = lboxT + lobjT + lclsT;
            out[1] = lboxT;
            out[2] = lobjT;
            out[3] = lclsT;
            g_obj = 0.f;
#pragma unroll
            for (int i = 0; i < 3; i++) {
                g_lcls[i] = 0.f; g_lbox[i] = 0.f; g_nb[i] = 0.f;
            }
            g_done = 0u;
            __threadfence();
        }
    }
}

extern "C" void kernel_launch(void* const* d_in, const int* in_sizes, int n_in,
                              void* d_out, int out_size) {
    const float* p0         = (const float*)d_in[0];
    const float* p1         = (const float*)d_in[1];
    const float* p2         = (const float*)d_in[2];
    const float* targets    = (const float*)d_in[3];
    const float* anchors    = (const float*)d_in[4];
    const float* image_size = (const float*)d_in[5];
    float* out = (float*)d_out;

    yolo_fused<<<NBLK, NTHR>>>(p0, p1, p2, targets, anchors, image_size, out);
}

// round 9
// speedup vs baseline: 1.0268x; 1.0268x over previous
#include <cuda_runtime.h>
#include <math.h>

#define BATCH 16
#define NA 3
#define NC 80
#define NCH 85
#define NT 512
#define THRESH 0.6f
#define EPSF 1e-7f

#define N0 307200
#define N1 76800
#define N2 19200

#define NBLK 444
#define NTHR 512

// float4 items per (b,a) plane and cumulative boundaries
#define PL0 1600
#define PL1 400
#define PL2 100
#define T0v 76800            // p0 float4 items
#define TE1 96000            // +19200 (p1)
#define TE2 100800           // +4800  (p2)

#define NLCLS 122880         // 3*512*80
#define LCLS_BASE 104448     // 204*512; lcls handled by blocks 204..443

#define W0 (1.0f / (float)N0)
#define W1 (1.0f / (float)N1)
#define W2 (1.0f / (float)N2)

__device__ float g_obj;
__device__ float g_lcls[3];
__device__ float g_lbox[3];
__device__ float g_nb[3];
__device__ unsigned g_done = 0;

__device__ __forceinline__ float softplus_fast(float x) {
    return fmaxf(x, 0.0f) + __logf(1.0f + __expf(-fabsf(x)));
}

__device__ __forceinline__ float sp4(float4 v) {
    return softplus_fast(v.x) + softplus_fast(v.y) +
           softplus_fast(v.z) + softplus_fast(v.w);
}

__device__ __forceinline__ float warp_red_f(float v) {
#pragma unroll
    for (int o = 16; o > 0; o >>= 1)
        v += __shfl_down_sync(0xffffffffu, v, o);
    return v;
}

__device__ __forceinline__ bool target_meta(
    const float* __restrict__ targets, const float* __restrict__ anchors,
    float im0, float im1, int s, int t, int H,
    unsigned& off, int& cell, int& a_out,
    float& gx, float& gy, float& gw, float& gh)
{
    const float* tg = targets + t * 6;
    float inv0 = (float)H / im0;
    float inv1 = (float)H / im1;

    gw = tg[4] * inv1;
    gh = tg[5] * inv0;

    float bi = -1.0f, bu = 1.0f;
    int arg = 0;
#pragma unroll
    for (int a = 0; a < 3; a++) {
        float aw = anchors[(s * 3 + a) * 2 + 0] * inv1;
        float ah = anchors[(s * 3 + a) * 2 + 1] * inv0;
        float inter = fminf(aw, gw) * fminf(ah, gh);
        float uni   = aw * ah + gw * gh - inter;
        if (inter * bu > bi * uni) { bi = inter; bu = uni; arg = a; }
    }
    if (!(bi > THRESH * bu)) return false;

    gx = tg[2] * inv1;
    gy = tg[3] * inv0;
    int b  = (int)tg[0];
    int gi = (int)gx;
    int gj = (int)gy;
    if (b  < 0) b  = 0; if (b  > BATCH - 1) b  = BATCH - 1;
    if (gi < 0) gi = 0; if (gi > H - 1)     gi = H - 1;
    if (gj < 0) gj = 0; if (gj > H - 1)     gj = H - 1;
    cell  = ((b * NA + arg) * H + gj) * H + gi;
    off   = (unsigned)((b * NA + arg) * NCH) * (unsigned)(H * H)
          + (unsigned)(gj * H + gi);
    a_out = arg;
    return true;
}

__global__ void __launch_bounds__(NTHR, 3)
yolo_fused(const float* __restrict__ p0,
           const float* __restrict__ p1,
           const float* __restrict__ p2,
           const float* __restrict__ targets,
           const float* __restrict__ anchors,
           const float* __restrict__ image_size,
           float* __restrict__ out)
{
    __shared__ float s_red[16][6];
    __shared__ int   table[1024];

    int tid  = threadIdx.x;
    int blk  = blockIdx.x;
    int lane = tid & 31;
    int wid  = tid >> 5;
    int gt   = blk * NTHR + tid;

    float im0 = image_size[0];
    float im1 = image_size[1];

    // ---------------- objectness: blocks 0..196 (one float4 per thread) ----------------
    const float4* p0v = reinterpret_cast<const float4*>(p0);
    const float4* p1v = reinterpret_cast<const float4*>(p1);
    const float4* p2v = reinterpret_cast<const float4*>(p2);

    float obj = 0.0f;
    if (gt < T0v) {
        int ba = gt / PL0;
        int r  = gt - ba * PL0;
        obj = W0 * sp4(p0v[(size_t)(ba * NCH + 4) * PL0 + r]);
    } else if (gt < TE1) {
        int i  = gt - T0v;
        int ba = i / PL1;
        int r  = i - ba * PL1;
        obj = W1 * sp4(p1v[(size_t)(ba * NCH + 4) * PL1 + r]);
    } else if (gt < TE2) {
        int i  = gt - TE1;
        int ba = i / PL2;
        int r  = i - ba * PL2;
        obj = W2 * sp4(p2v[(size_t)(ba * NCH + 4) * PL2 + r]);
    }

    // ---------------- lcls: blocks 204..443 (one item per thread) ----------------
    float lc = 0.0f;
    int sA = 2;
    int li = gt - LCLS_BASE;
    if (li >= 0 && li < NLCLS) {
        int p = li / NC;
        int j = li - p * NC;
        sA = p >> 9;            // warp uniform
        int t = p & 511;
        int H = (sA == 0) ? 80 : ((sA == 1) ? 40 : 20);

        unsigned off; int cell, a_s; float gx, gy, gw, gh;
        if (target_meta(targets, anchors, im0, im1, sA, t, H,
                        off, cell, a_s, gx, gy, gw, gh)) {
            int HW = H * H;
            const float* pis = (sA == 0) ? p0 : ((sA == 1) ? p1 : p2);
            float x = pis[off + (unsigned)(5 + j) * (unsigned)HW];
            int cls = (int)targets[t * 6 + 1] - 1;
            lc = softplus_fast(x) - ((j == cls) ? x : 0.0f);
        }
    }

    // ---------------- pair work: blocks 0-2 only ----------------
    float lbox = 0.0f, nb = 0.0f;
    bool isTgt = (blk < 3);
    if (isTgt) {
        table[tid] = -1;
        table[tid + 512] = -1;
        __syncthreads();

        int s = blk, t = tid;
        int H = (s == 0) ? 80 : ((s == 1) ? 40 : 20);
        unsigned off; int cell, a_s; float gx, gy, gw, gh;
        if (target_meta(targets, anchors, im0, im1, s, t, H,
                        off, cell, a_s, gx, gy, gw, gh)) {
            nb = 1.0f;
            int HW = H * H;
            const float* pis = (s == 0) ? p0 : ((s == 1) ? p1 : p2);
            float inv0 = (float)H / im0;
            float inv1 = (float)H / im1;
            float ws   = (s == 0) ? W0 : ((s == 1) ? W1 : W2);

            float aw = anchors[(s * 3 + a_s) * 2 + 0] * inv1;
            float ah = anchors[(s * 3 + a_s) * 2 + 1] * inv0;

            float ps0 = pis[off];
            float ps1 = pis[off + HW];
            float ps2 = pis[off + 2 * HW];
            float ps3 = pis[off + 3 * HW];
            float lg  = pis[off + 4 * HW];

            float pcx = 1.0f / (1.0f + __expf(-ps0));
            float pcy = 1.0f / (1.0f + __expf(-ps1));
            float pw  = fminf(__expf(ps2), 1000.0f) * aw;
            float ph  = fminf(__expf(ps3), 1000.0f) * ah;

            float tcx = gx - floorf(gx);
            float tcy = gy - floorf(gy);

            float px1 = pcx - pw * 0.5f, py1 = pcy - ph * 0.5f;
            float px2 = pcx + pw * 0.5f, py2 = pcy + ph * 0.5f;
            float tx1 = tcx - gw * 0.5f, ty1 = tcy - gh * 0.5f;
            float tx2 = tcx + gw * 0.5f, ty2 = tcy + gh * 0.5f;

            float iw = fmaxf(fminf(px2, tx2) - fmaxf(px1, tx1), 0.0f);
            float ih = fmaxf(fminf(py2, ty2) - fmaxf(py1, ty1), 0.0f);
            float inter = iw * ih;
            float uni   = pw * ph + gw * gh - inter + EPSF;
            float iou   = inter / uni;
            float cw = fmaxf(px2, tx2) - fminf(px1, tx1);
            float ch = fmaxf(py2, ty2) - fminf(py1, ty1);
            float c_area = cw * ch + EPSF;
            float giou = iou - (c_area - uni) / c_area;

            lbox = 1.0f - giou;

            unsigned hsh = ((unsigned)cell * 2654435761u) & 1023u;
            bool owner = false;
            while (true) {
                int prev = atomicCAS(&table[hsh], -1, cell);
                if (prev == -1)   { owner = true; break; }
                if (prev == cell) { break; }
                hsh = (hsh + 1) & 1023u;
            }
            if (owner) obj += -lg * ws;   // folded tobj correction
        }
    }

    // ---------------- reductions (float, pairwise) ----------------
    obj = warp_red_f(obj);
    lc  = warp_red_f(lc);
    if (isTgt) { lbox = warp_red_f(lbox); nb = warp_red_f(nb); }

    if (lane == 0) {
        s_red[wid][0] = obj;
        s_red[wid][1] = (sA == 0) ? lc : 0.f;
        s_red[wid][2] = (sA == 1) ? lc : 0.f;
        s_red[wid][3] = (sA == 2) ? lc : 0.f;
        s_red[wid][4] = isTgt ? lbox : 0.f;
        s_red[wid][5] = isTgt ? nb   : 0.f;
    }
    __syncthreads();

    if (wid < 6) {
        float v = (lane < 16) ? s_red[lane][wid] : 0.0f;
        v = warp_red_f(v);
        if (lane == 0) {
            if      (wid == 0) { if (v != 0.0f) atomicAdd(&g_obj, v); }
            else if (wid <  4) { if (v != 0.0f) atomicAdd(&g_lcls[wid - 1], v); }
            else if (isTgt) {
                if (wid == 4) g_lbox[blk] = v;   // single writer per scale
                else          g_nb[blk]   = v;
            }
        }
    }

    // ---------------- finisher ----------------
    __syncthreads();
    if (tid == 0) {
        __threadfence();
        unsigned old = atomicAdd(&g_done, 1u);
        if (old == NBLK - 1) {
            __threadfence();
            float lboxT = 0.f, lclsT = 0.f;
#pragma unroll
            for (int i = 0; i < 3; i++) {
                float nbv = fmaxf(g_nb[i], 1.0f);
                lboxT += g_lbox[i] / nbv;
                lclsT += g_lcls[i] / (nbv * (float)NC);
            }
            float lobjT = g_obj * 64.3f;
            lboxT *= 3.54f;
            lclsT *= 37.4f;
            out[0] = lboxT + lobjT + lclsT;
            out[1] = lboxT;
            out[2] = lobjT;
            out[3] = lclsT;
            g_obj = 0.f;
#pragma unroll
            for (int i = 0; i < 3; i++) {
                g_lcls[i] = 0.f; g_lbox[i] = 0.f; g_nb[i] = 0.f;
            }
            g_done = 0u;
            __threadfence();
        }
    }
}

extern "C" void kernel_launch(void* const* d_in, const int* in_sizes, int n_in,
                              void* d_out, int out_size) {
    const float* p0         = (const float*)d_in[0];
    const float* p1         = (const float*)d_in[1];
    const float* p2         = (const float*)d_in[2];
    const float* targets    = (const float*)d_in[3];
    const float* anchors    = (const float*)d_in[4];
    const float* image_size = (const float*)d_in[5];
    float* out = (float*)d_out;

    yolo_fused<<<NBLK, NTHR>>>(p0, p1, p2, targets, anchors, image_size, out);
}

// round 10
// speedup vs baseline: 1.2684x; 1.2353x over previous
#include <cuda_runtime.h>
#include <math.h>

#define BATCH 16
#define NA 3
#define NC 80
#define NCH 85
#define NT 512
#define THRESH 0.6f
#define EPSF 1e-7f

#define N0 307200
#define N1 76800
#define N2 19200

#define NBLK 296
#define NTHR 512

// float4 items per (b,a) plane and cumulative boundaries
#define PL0 1600
#define PL1 400
#define PL2 100
#define T0v 76800
#define TE1 96000
#define TE2 100800

#define NLCLS 122880        // 3*512*80 ( = 240 blocks * 512 )
#define NPMAX 1536          // total (scale,target) pairs

#define W0 (1.0f / (float)N0)
#define W1 (1.0f / (float)N1)
#define W2 (1.0f / (float)N2)

__device__ float g_obj;
__device__ float g_lcls[3];
__device__ float g_lbox[3];
__device__ float g_nb[3];
__device__ unsigned g_done = 0;

__device__ __forceinline__ float softplus_fast(float x) {
    return fmaxf(x, 0.0f) + __logf(1.0f + __expf(-fabsf(x)));
}

__device__ __forceinline__ float sp4(float4 v) {
    return softplus_fast(v.x) + softplus_fast(v.y) +
           softplus_fast(v.z) + softplus_fast(v.w);
}

__device__ __forceinline__ float warp_red_f(float v) {
#pragma unroll
    for (int o = 16; o > 0; o >>= 1)
        v += __shfl_down_sync(0xffffffffu, v, o);
    return v;
}

__device__ __forceinline__ bool target_meta(
    const float* __restrict__ targets, const float* __restrict__ anchors,
    float im0, float im1, int s, int t, int H,
    unsigned& off, int& cell, int& a_out,
    float& gx, float& gy, float& gw, float& gh)
{
    const float* tg = targets + t * 6;
    float inv0 = (float)H / im0;
    float inv1 = (float)H / im1;

    gw = tg[4] * inv1;
    gh = tg[5] * inv0;

    float bi = -1.0f, bu = 1.0f;
    int arg = 0;
#pragma unroll
    for (int a = 0; a < 3; a++) {
        float aw = anchors[(s * 3 + a) * 2 + 0] * inv1;
        float ah = anchors[(s * 3 + a) * 2 + 1] * inv0;
        float inter = fminf(aw, gw) * fminf(ah, gh);
        float uni   = aw * ah + gw * gh - inter;
        if (inter * bu > bi * uni) { bi = inter; bu = uni; arg = a; }
    }
    if (!(bi > THRESH * bu)) return false;

    gx = tg[2] * inv1;
    gy = tg[3] * inv0;
    int b  = (int)tg[0];
    int gi = (int)gx;
    int gj = (int)gy;
    if (b  < 0) b  = 0; if (b  > BATCH - 1) b  = BATCH - 1;
    if (gi < 0) gi = 0; if (gi > H - 1)     gi = H - 1;
    if (gj < 0) gj = 0; if (gj > H - 1)     gj = H - 1;
    cell  = ((b * NA + arg) * H + gj) * H + gi;
    off   = (unsigned)((b * NA + arg) * NCH) * (unsigned)(H * H)
          + (unsigned)(gj * H + gi);
    a_out = arg;
    return true;
}

__global__ void __launch_bounds__(NTHR, 2)
yolo_fused(const float* __restrict__ p0,
           const float* __restrict__ p1,
           const float* __restrict__ p2,
           const float* __restrict__ targets,
           const float* __restrict__ anchors,
           const float* __restrict__ image_size,
           float* __restrict__ out)
{
    __shared__ float    s_red[16][6];
    __shared__ int      table[1024];
    __shared__ unsigned s_moff[8];     // 0xFFFFFFFF = invalid
    __shared__ int      s_mcls[8];

    int tid  = threadIdx.x;
    int blk  = blockIdx.x;
    int lane = tid & 31;
    int wid  = tid >> 5;
    int gt   = blk * NTHR + tid;

    float im0 = image_size[0];
    float im1 = image_size[1];

    bool isTgt  = (blk < 3);
    bool isLcls = (blk < 240);         // lcls items = gt in [0, 122880)
    int  pf     = (blk * NTHR) / NC;   // first pair index this block touches

    // ---------------- per-block metadata (threads 0-7) ----------------
    if (isLcls && tid < 8) {
        unsigned moff = 0xFFFFFFFFu;
        int mcls = 0;
        int p = pf + tid;
        if (p < NPMAX) {
            int s = p >> 9;
            int t = p & 511;
            int H = (s == 0) ? 80 : ((s == 1) ? 40 : 20);
            unsigned off; int cell, a_s; float gx, gy, gw, gh;
            if (target_meta(targets, anchors, im0, im1, s, t, H,
                            off, cell, a_s, gx, gy, gw, gh)) {
                moff = off;
                mcls = (int)targets[t * 6 + 1] - 1;
            }
        }
        s_moff[tid] = moff;
        s_mcls[tid] = mcls;
    }
    if (isTgt) {
        table[tid] = -1;
        table[tid + 512] = -1;
    }

    // ---------------- objectness: one float4 per thread ----------------
    const float4* p0v = reinterpret_cast<const float4*>(p0);
    const float4* p1v = reinterpret_cast<const float4*>(p1);
    const float4* p2v = reinterpret_cast<const float4*>(p2);

    float obj = 0.0f;
    if (gt < T0v) {
        int ba = gt / PL0;
        int r  = gt - ba * PL0;
        obj = W0 * sp4(p0v[(size_t)(ba * NCH + 4) * PL0 + r]);
    } else if (gt < TE1) {
        int i  = gt - T0v;
        int ba = i / PL1;
        int r  = i - ba * PL1;
        obj = W1 * sp4(p1v[(size_t)(ba * NCH + 4) * PL1 + r]);
    } else if (gt < TE2) {
        int i  = gt - TE1;
        int ba = i / PL2;
        int r  = i - ba * PL2;
        obj = W2 * sp4(p2v[(size_t)(ba * NCH + 4) * PL2 + r]);
    }

    __syncthreads();   // metadata + table ready

    // ---------------- lcls: one gather per thread via shared metadata ----------------
    float lc = 0.0f;
    int sA = 2;
    if (isLcls) {
        int p = gt / NC;
        int j = gt - p * NC;
        sA = p >> 9;                    // warp uniform (boundaries 40960/81920)
        unsigned moff = s_moff[p - pf];
        if (moff != 0xFFFFFFFFu) {
            int H  = (sA == 0) ? 80 : ((sA == 1) ? 40 : 20);
            int HW = H * H;
            const float* pis = (sA == 0) ? p0 : ((sA == 1) ? p1 : p2);
            float x = pis[moff + (unsigned)(5 + j) * (unsigned)HW];
            lc = softplus_fast(x) - ((j == s_mcls[p - pf]) ? x : 0.0f);
        }
    }

    // ---------------- pair work: blocks 0-2 only ----------------
    float lbox = 0.0f, nb = 0.0f;
    if (isTgt) {
        int s = blk, t = tid;
        int H = (s == 0) ? 80 : ((s == 1) ? 40 : 20);
        unsigned off; int cell, a_s; float gx, gy, gw, gh;
        if (target_meta(targets, anchors, im0, im1, s, t, H,
                        off, cell, a_s, gx, gy, gw, gh)) {
            nb = 1.0f;
            int HW = H * H;
            const float* pis = (s == 0) ? p0 : ((s == 1) ? p1 : p2);
            float inv0 = (float)H / im0;
            float inv1 = (float)H / im1;
            float ws   = (s == 0) ? W0 : ((s == 1) ? W1 : W2);

            float aw = anchors[(s * 3 + a_s) * 2 + 0] * inv1;
            float ah = anchors[(s * 3 + a_s) * 2 + 1] * inv0;

            float ps0 = pis[off];
            float ps1 = pis[off + HW];
            float ps2 = pis[off + 2 * HW];
            float ps3 = pis[off + 3 * HW];
            float lg  = pis[off + 4 * HW];

            float pcx = 1.0f / (1.0f + __expf(-ps0));
            float pcy = 1.0f / (1.0f + __expf(-ps1));
            float pw  = fminf(__expf(ps2), 1000.0f) * aw;
            float ph  = fminf(__expf(ps3), 1000.0f) * ah;

            float tcx = gx - floorf(gx);
            float tcy = gy - floorf(gy);

            float px1 = pcx - pw * 0.5f, py1 = pcy - ph * 0.5f;
            float px2 = pcx + pw * 0.5f, py2 = pcy + ph * 0.5f;
            float tx1 = tcx - gw * 0.5f, ty1 = tcy - gh * 0.5f;
            float tx2 = tcx + gw * 0.5f, ty2 = tcy + gh * 0.5f;

            float iw = fmaxf(fminf(px2, tx2) - fmaxf(px1, tx1), 0.0f);
            float ih = fmaxf(fminf(py2, ty2) - fmaxf(py1, ty1), 0.0f);
            float inter = iw * ih;
            float uni   = pw * ph + gw * gh - inter + EPSF;
            float iou   = inter / uni;
            float cw = fmaxf(px2, tx2) - fminf(px1, tx1);
            float ch = fmaxf(py2, ty2) - fminf(py1, ty1);
            float c_area = cw * ch + EPSF;
            float giou = iou - (c_area - uni) / c_area;

            lbox = 1.0f - giou;

            unsigned hsh = ((unsigned)cell * 2654435761u) & 1023u;
            bool owner = false;
            while (true) {
                int prev = atomicCAS(&table[hsh], -1, cell);
                if (prev == -1)   { owner = true; break; }
                if (prev == cell) { break; }
                hsh = (hsh + 1) & 1023u;
            }
            if (owner) obj += -lg * ws;   // folded tobj correction
        }
    }

    // ---------------- reductions (float, pairwise) ----------------
    obj = warp_red_f(obj);
    lc  = warp_red_f(lc);
    if (isTgt) { lbox = warp_red_f(lbox); nb = warp_red_f(nb); }

    if (lane == 0) {
        s_red[wid][0] = obj;
        s_red[wid][1] = (sA == 0) ? lc : 0.f;
        s_red[wid][2] = (sA == 1) ? lc : 0.f;
        s_red[wid][3] = (sA == 2) ? lc : 0.f;
        s_red[wid][4] = isTgt ? lbox : 0.f;
        s_red[wid][5] = isTgt ? nb   : 0.f;
    }
    __syncthreads();

    if (wid < 6) {
        float v = (lane < 16) ? s_red[lane][wid] : 0.0f;
        v = warp_red_f(v);
        if (lane == 0) {
            if      (wid == 0) { if (v != 0.0f) atomicAdd(&g_obj, v); }
            else if (wid <  4) { if (v != 0.0f) atomicAdd(&g_lcls[wid - 1], v); }
            else if (isTgt) {
                if (wid == 4) g_lbox[blk] = v;   // single writer per scale
                else          g_nb[blk]   = v;
            }
        }
    }

    // ---------------- finisher ----------------
    __syncthreads();
    if (tid == 0) {
        __threadfence();
        unsigned old = atomicAdd(&g_done, 1u);
        if (old == NBLK - 1) {
            __threadfence();
            float lboxT = 0.f, lclsT = 0.f;
#pragma unroll
            for (int i = 0; i < 3; i++) {
                float nbv = fmaxf(g_nb[i], 1.0f);
                lboxT += g_lbox[i] / nbv;
                lclsT += g_lcls[i] / (nbv * (float)NC);
            }
            float lobjT = g_obj * 64.3f;
            lboxT *= 3.54f;
            lclsT *= 37.4f;
            out[0] = lboxT + lobjT + lclsT;
            out[1] = lboxT;
            out[2] = lobjT;
            out[3] = lclsT;
            g_obj = 0.f;
#pragma unroll
            for (int i = 0; i < 3; i++) {
                g_lcls[i] = 0.f; g_lbox[i] = 0.f; g_nb[i] = 0.f;
            }
            g_done = 0u;
            __threadfence();
        }
    }
}

extern "C" void kernel_launch(void* const* d_in, const int* in_sizes, int n_in,
                              void* d_out, int out_size) {
    const float* p0         = (const float*)d_in[0];
    const float* p1         = (const float*)d_in[1];
    const float* p2         = (const float*)d_in[2];
    const float* targets    = (const float*)d_in[3];
    const float* anchors    = (const float*)d_in[4];
    const float* image_size = (const float*)d_in[5];
    float* out = (float*)d_out;

    yolo_fused<<<NBLK, NTHR>>>(p0, p1, p2, targets, anchors, image_size, out);
}